// round 11
// baseline (speedup 1.0000x reference)
#include <cuda_runtime.h>
#include <math.h>

#define BB 32
#define SS 128
#define NC 128
#define DD 64
#define II 256
#define OD 8192   // NC*DD

__device__ float g_PE1[NC * DD];
__device__ float g_PE2[SS * OD];        // 4 MB
__device__ float g_P  [BB * SS * DD];
__device__ float g_Su [BB * SS];
__device__ float g_C  [BB * NC * SS];
__device__ float g_T  [BB * NC * DD];
__device__ float g_V  [BB * NC * DD];
__device__ float g_Bl [BB * NC * SS];

// ---------------------------------------------------------------------------
// Merged init: blocks 0..511 = PE tables + initC; blocks 512..767 = gemmP.
// ---------------------------------------------------------------------------
__global__ void __launch_bounds__(256) k_init(const float* __restrict__ u,
                                              const float* __restrict__ W,
                                              const float* __restrict__ mask) {
    __shared__ float shU[16][II];   // used only by gemmP branch
    if (blockIdx.x < 512) {
        const float LN1E4 = 9.210340371976184f;
        int s = blockIdx.x >> 2;
        int chunk = blockIdx.x & 3;
        int base = chunk * 1024;
        #pragma unroll
        for (int j = 0; j < 4; j++) {
            int k = base + j * 256 + threadIdx.x;
            float invf = __expf(-(float)k * (LN1E4 / 4096.0f));
            float sv, cv;
            __sincosf((float)s * invf, &sv, &cv);
            *(float2*)&g_PE2[s * OD + 2 * k] = make_float2(sv, cv);
        }
        if (chunk == 0 && threadIdx.x < 32) {
            int k = threadIdx.x;
            float invf = __expf(-(float)k * (LN1E4 / 32.0f));
            float sv, cv;
            __sincosf((float)s * invf, &sv, &cv);
            *(float2*)&g_PE1[s * DD + 2 * k] = make_float2(sv, cv);
        }
        for (int idx = blockIdx.x * 256 + threadIdx.x; idx < BB * NC * SS;
             idx += 512 * 256) {
            int s2 = idx & (SS - 1);
            int b  = idx >> 14;
            g_C[idx] = mask[b * SS + s2] * (1.0f / 128.0f);
        }
        return;
    }
    // ---- gemmP: P = u @ W, Su = rowsum(u) ----
    int row0 = (blockIdx.x - 512) * 16;
    for (int idx = threadIdx.x; idx < 16 * 64; idx += 256) {
        int r = idx >> 6, i = idx & 63;
        *(float4*)&shU[r][i * 4] = *(const float4*)&u[(row0 + r) * II + i * 4];
    }
    __syncthreads();
    int d = threadIdx.x & 63, g = threadIdx.x >> 6;
    const float4* u0 = (const float4*)&shU[g][0];
    const float4* u1 = (const float4*)&shU[g + 4][0];
    const float4* u2 = (const float4*)&shU[g + 8][0];
    const float4* u3 = (const float4*)&shU[g + 12][0];
    float a0 = 0, a1 = 0, a2 = 0, a3 = 0;
    #pragma unroll 8
    for (int i4 = 0; i4 < II / 4; i4++) {
        float4 f0 = u0[i4], f1 = u1[i4], f2 = u2[i4], f3 = u3[i4];
        float w0 = __ldg(&W[(i4 * 4 + 0) * DD + d]);
        float w1 = __ldg(&W[(i4 * 4 + 1) * DD + d]);
        float w2 = __ldg(&W[(i4 * 4 + 2) * DD + d]);
        float w3 = __ldg(&W[(i4 * 4 + 3) * DD + d]);
        a0 += f0.x * w0 + f0.y * w1 + f0.z * w2 + f0.w * w3;
        a1 += f1.x * w0 + f1.y * w1 + f1.z * w2 + f1.w * w3;
        a2 += f2.x * w0 + f2.y * w1 + f2.z * w2 + f2.w * w3;
        a3 += f3.x * w0 + f3.y * w1 + f3.z * w2 + f3.w * w3;
    }
    g_P[(row0 + g) * DD + d]      = a0;
    g_P[(row0 + g + 4) * DD + d]  = a1;
    g_P[(row0 + g + 8) * DD + d]  = a2;
    g_P[(row0 + g + 12) * DD + d] = a3;
    int r = threadIdx.x >> 4, t = threadIdx.x & 15;
    float sm = 0.f;
    for (int i = t; i < II; i += 16) sm += shU[r][i];
    sm += __shfl_xor_sync(0xffffffffu, sm, 8);
    sm += __shfl_xor_sync(0xffffffffu, sm, 4);
    sm += __shfl_xor_sync(0xffffffffu, sm, 2);
    sm += __shfl_xor_sync(0xffffffffu, sm, 1);
    if (t == 0) g_Su[row0 + r] = sm;
}

// ---------------------------------------------------------------------------
// Output terms 1+2 (full s): T[b,n,d] = sum_s c*P + (sum_s c*Su)*PE1[n,d]
// grid = 32 b * 32 ntile(4n) = 1024. P read directly (coalesced LDG, L2-hot).
// ---------------------------------------------------------------------------
__global__ void __launch_bounds__(256) k_outA() {
    __shared__ float4 shC4[4][32];    // 4 n x 128 s
    __shared__ float4 shSu4[32];
    int b = blockIdx.x >> 5, n0 = (blockIdx.x & 31) * 4;
    if (threadIdx.x < 128) {
        int nr = threadIdx.x >> 5, sc = threadIdx.x & 31;
        shC4[nr][sc] = *(const float4*)&g_C[(b * NC + n0 + nr) * SS + sc * 4];
    } else if (threadIdx.x < 160) {
        int sc = threadIdx.x - 128;
        shSu4[sc] = *(const float4*)&g_Su[b * SS + sc * 4];
    }
    __syncthreads();
    int d = threadIdx.x & 63, g = threadIdx.x >> 6;
    const float* Pb = &g_P[b * SS * DD + d];
    float a = 0.f, q = 0.f;
    #pragma unroll 4
    for (int s4 = 0; s4 < 32; s4++) {
        float4 f  = shC4[g][s4];
        float4 su = shSu4[s4];
        float p0 = __ldg(Pb + (s4 * 4 + 0) * DD);
        float p1 = __ldg(Pb + (s4 * 4 + 1) * DD);
        float p2 = __ldg(Pb + (s4 * 4 + 2) * DD);
        float p3 = __ldg(Pb + (s4 * 4 + 3) * DD);
        a += f.x * p0 + f.y * p1 + f.z * p2 + f.w * p3;
        q += f.x * su.x + f.y * su.y + f.z * su.z + f.w * su.w;
    }
    int n = n0 + g;
    g_T[(b * NC + n) * DD + d] = a + q * g_PE1[n * DD + d];
}

// ---------------------------------------------------------------------------
// Output term 3 + squash + fused logit term 3.
// grid = 128 n * 8 btile(4b) = 1024. shPE2 pitched to 68.
// Phase 1: val = T + sum_s c*PE2; V = squash(val)   (thread = (d, b))
// Phase 2: Bl[b,n,s] = sum_d V*PE2                  (thread = (s, b-pair))
// ---------------------------------------------------------------------------
__global__ void __launch_bounds__(256) k_outB(float* __restrict__ dst, int final_) {
    __shared__ float  shPE2[SS * 68];   // 34.8 KB
    __shared__ float4 shC4[4][32];
    __shared__ float  shV[4 * DD];      // 1 KB
    __shared__ float  shRed[4][2];
    int n  = blockIdx.x >> 3;
    int b0 = (blockIdx.x & 7) * 4;
    float* Vout = final_ ? dst : g_V;
    for (int idx = threadIdx.x; idx < SS * 16; idx += 256) {
        int s = idx >> 4, c = idx & 15;
        *(float4*)&shPE2[s * 68 + c * 4] = *(const float4*)&g_PE2[s * OD + n * DD + c * 4];
    }
    if (threadIdx.x < 128) {
        int bl = threadIdx.x >> 5, sc = threadIdx.x & 31;
        shC4[bl][sc] = *(const float4*)&g_C[((b0 + bl) * NC + n) * SS + sc * 4];
    }
    __syncthreads();
    int d = threadIdx.x & 63, g = threadIdx.x >> 6;
    int lane = threadIdx.x & 31, wig = (threadIdx.x >> 5) & 1;
    float a = 0.f;
    #pragma unroll 4
    for (int s4 = 0; s4 < 32; s4++) {
        float4 f = shC4[g][s4];
        float p0 = shPE2[(s4 * 4 + 0) * 68 + d];
        float p1 = shPE2[(s4 * 4 + 1) * 68 + d];
        float p2 = shPE2[(s4 * 4 + 2) * 68 + d];
        float p3 = shPE2[(s4 * 4 + 3) * 68 + d];
        a += f.x * p0 + f.y * p1 + f.z * p2 + f.w * p3;
    }
    int b = b0 + g;
    float val = g_T[(b * NC + n) * DD + d] + a;
    float ssq = val * val;
    #pragma unroll
    for (int off = 16; off; off >>= 1)
        ssq += __shfl_xor_sync(0xffffffffu, ssq, off);
    if (lane == 0) shRed[g][wig] = ssq;
    __syncthreads();
    float tt = shRed[g][0] + shRed[g][1];
    float sc = tt / (1.0f + tt) * rsqrtf(tt + 1e-7f);
    float vw = sc * val;
    Vout[(b * NC + n) * DD + d] = vw;
    if (final_) return;
    shV[g * DD + d] = vw;
    __syncthreads();
    // Phase 2: logit term 3 for this (n, 4-b tile)
    int s = threadIdx.x & 127, h = threadIdx.x >> 7;
    int bl = h * 2;
    const float4* pr = (const float4*)&shPE2[s * 68];
    const float4* w0 = (const float4*)&shV[(bl + 0) * DD];
    const float4* w1 = (const float4*)&shV[(bl + 1) * DD];
    float r0 = 0.f, r1 = 0.f;
    #pragma unroll
    for (int d4 = 0; d4 < 16; d4++) {
        float4 p = pr[d4];
        float4 x0 = w0[d4], x1 = w1[d4];
        r0 += p.x * x0.x + p.y * x0.y + p.z * x0.z + p.w * x0.w;
        r1 += p.x * x1.x + p.y * x1.y + p.z * x1.z + p.w * x1.w;
    }
    g_Bl[((b0 + bl + 0) * NC + n) * SS + s] = r0;
    g_Bl[((b0 + bl + 1) * NC + n) * SS + s] = r1;
}

// ---------------------------------------------------------------------------
// Logit terms 1+2 (accumulate onto term 3). grid = 32 b * 16 ntile * 2 shalf
// = 1024; 8 n x 64 s per block. shP halved to 17.4 KB.
// ---------------------------------------------------------------------------
__global__ void __launch_bounds__(256) k_bA() {
    __shared__ float shP[64 * 68];   // 17.4 KB
    __shared__ float shV[8 * DD];    // 2 KB
    __shared__ float shSu[64];
    __shared__ float shSc[8];
    int sh = blockIdx.x & 1;
    int n0 = ((blockIdx.x >> 1) & 15) * 8;
    int b  = blockIdx.x >> 5;
    int sbase = sh * 64;
    for (int idx = threadIdx.x; idx < 64 * 16; idx += 256) {
        int s = idx >> 4, c = idx & 15;
        *(float4*)&shP[s * 68 + c * 4] = *(const float4*)&g_P[(b * SS + sbase + s) * DD + c * 4];
    }
    for (int idx = threadIdx.x; idx < 8 * 16; idx += 256)
        *(float4*)&shV[idx * 4] = *(const float4*)&g_V[(b * NC + n0) * DD + idx * 4];
    if (threadIdx.x < 64) shSu[threadIdx.x] = g_Su[b * SS + sbase + threadIdx.x];
    __syncthreads();
    {
        int w = threadIdx.x >> 5, lane = threadIdx.x & 31;
        float t = shV[w * DD + lane]      * g_PE1[(n0 + w) * DD + lane]
                + shV[w * DD + 32 + lane] * g_PE1[(n0 + w) * DD + 32 + lane];
        #pragma unroll
        for (int off = 16; off; off >>= 1)
            t += __shfl_xor_sync(0xffffffffu, t, off);
        if (lane == 0) shSc[w] = t;
    }
    __syncthreads();
    int sl = threadIdx.x & 63, h = threadIdx.x >> 6;   // 4 groups x 2 n
    int s = sbase + sl;
    int nl = h * 2;
    const float4* pr = (const float4*)&shP[sl * 68];
    const float4* v0 = (const float4*)&shV[(nl + 0) * DD];
    const float4* v1 = (const float4*)&shV[(nl + 1) * DD];
    float a0 = 0.f, a1 = 0.f;
    #pragma unroll
    for (int d4 = 0; d4 < 16; d4++) {
        float4 p = pr[d4];
        float4 x0 = v0[d4], x1 = v1[d4];
        a0 += p.x * x0.x + p.y * x0.y + p.z * x0.z + p.w * x0.w;
        a1 += p.x * x1.x + p.y * x1.y + p.z * x1.z + p.w * x1.w;
    }
    float su = shSu[sl];
    g_Bl[(b * NC + n0 + nl + 0) * SS + s] += a0 + su * shSc[nl + 0];
    g_Bl[(b * NC + n0 + nl + 1) * SS + s] += a1 + su * shSc[nl + 1];
}

// ---------------------------------------------------------------------------
// Softmax over n. grid = 128, 256 threads (8 warps x 16 n).
// ---------------------------------------------------------------------------
__global__ void __launch_bounds__(256) k_softmax(const float* __restrict__ mask) {
    __shared__ float red[2][8][32];
    int b = blockIdx.x >> 2, s0 = (blockIdx.x & 3) * 32;
    int lane = threadIdx.x & 31, w = threadIdx.x >> 5;
    int s = s0 + lane;
    float v[16];
    float mx = -1e30f;
    #pragma unroll
    for (int j = 0; j < 16; j++) {
        v[j] = g_Bl[(b * NC + w * 16 + j) * SS + s];
        mx = fmaxf(mx, v[j]);
    }
    red[0][w][lane] = mx;
    __syncthreads();
    mx = red[0][0][lane];
    #pragma unroll
    for (int w2 = 1; w2 < 8; w2++) mx = fmaxf(mx, red[0][w2][lane]);
    float sum = 0.f;
    #pragma unroll
    for (int j = 0; j < 16; j++) { v[j] = __expf(v[j] - mx); sum += v[j]; }
    red[1][w][lane] = sum;
    __syncthreads();
    sum = red[1][0][lane];
    #pragma unroll
    for (int w2 = 1; w2 < 8; w2++) sum += red[1][w2][lane];
    float scale = mask[b * SS + s] / sum;
    #pragma unroll
    for (int j = 0; j < 16; j++)
        g_C[(b * NC + w * 16 + j) * SS + s] = v[j] * scale;
}

// ---------------------------------------------------------------------------
extern "C" void kernel_launch(void* const* d_in, const int* in_sizes, int n_in,
                              void* d_out, int out_size) {
    const float* u    = (const float*)d_in[0];
    const float* mask = (const float*)d_in[1];
    const float* W    = (const float*)d_in[2];
    float* out = (float*)d_out;

    k_init<<<768, 256>>>(u, W, mask);

    for (int it = 0; it < 3; it++) {
        k_outA<<<1024, 256>>>();
        k_outB<<<1024, 256>>>(out, it == 2 ? 1 : 0);
        if (it < 2) {
            k_bA<<<1024, 256>>>();
            k_softmax<<<128, 256>>>(mask);
        }
    }
}

// round 12
// speedup vs baseline: 1.1903x; 1.1903x over previous
#include <cuda_runtime.h>
#include <math.h>

#define BB 32
#define SS 128
#define NC 128
#define DD 64
#define II 256
#define OD 8192   // NC*DD
#define TOFF (BB*NC*DD)

__device__ float g_PE1[NC * DD];
__device__ float g_PE2[SS * OD];        // 4 MB
__device__ float g_P  [BB * SS * DD];
__device__ float g_Su [BB * SS];
__device__ float g_q  [BB];
__device__ float g_C  [BB * NC * SS];
__device__ float g_T  [2 * BB * NC * DD];
__device__ float g_V  [BB * NC * DD];
__device__ float g_Bl [BB * NC * SS];

// ---------------------------------------------------------------------------
// Init, 288 blocks:
//   0..15   : PE2 via rotation recurrence along s (4096 threads, 1 sincos each)
//   16..31  : PE1 direct (4096 entries)
//   32..287 : gemmP (P = u @ W, Su = rowsum(u))
// ---------------------------------------------------------------------------
__global__ void __launch_bounds__(256) k_init(const float* __restrict__ u,
                                              const float* __restrict__ W) {
    __shared__ float shU[16][II];   // gemm branch only
    const float LN1E4 = 9.210340371976184f;
    if (blockIdx.x < 16) {
        // PE2[s, 2k]=sin(s*th_k), [2k+1]=cos(s*th_k); recurrence over s.
        int k = blockIdx.x * 256 + threadIdx.x;      // 0..4095
        float th = expf(-(float)k * (LN1E4 / 4096.0f));
        float sv, cv;
        sincosf(th, &sv, &cv);
        float sc = 0.f, cc = 1.f;                    // s = 0
        float2* dst = (float2*)g_PE2;
        #pragma unroll 4
        for (int s = 0; s < SS; s++) {
            dst[s * (OD / 2) + k] = make_float2(sc, cc);
            float ns = sc * cv + cc * sv;
            float nc = cc * cv - sc * sv;
            sc = ns; cc = nc;
        }
        return;
    }
    if (blockIdx.x < 32) {
        int idx = (blockIdx.x - 16) * 256 + threadIdx.x;  // 0..4095
        int n = idx >> 5, kk = idx & 31;
        float th = expf(-(float)kk * (LN1E4 / 32.0f));
        float sv, cv;
        sincosf((float)n * th, &sv, &cv);
        *(float2*)&g_PE1[n * DD + 2 * kk] = make_float2(sv, cv);
        return;
    }
    // ---- gemmP ----
    int row0 = (blockIdx.x - 32) * 16;
    for (int idx = threadIdx.x; idx < 16 * 64; idx += 256) {
        int r = idx >> 6, i = idx & 63;
        *(float4*)&shU[r][i * 4] = *(const float4*)&u[(row0 + r) * II + i * 4];
    }
    __syncthreads();
    int d = threadIdx.x & 63, g = threadIdx.x >> 6;
    const float4* u0 = (const float4*)&shU[g][0];
    const float4* u1 = (const float4*)&shU[g + 4][0];
    const float4* u2 = (const float4*)&shU[g + 8][0];
    const float4* u3 = (const float4*)&shU[g + 12][0];
    float a0 = 0, a1 = 0, a2 = 0, a3 = 0;
    #pragma unroll 8
    for (int i4 = 0; i4 < II / 4; i4++) {
        float4 f0 = u0[i4], f1 = u1[i4], f2 = u2[i4], f3 = u3[i4];
        float w0 = __ldg(&W[(i4 * 4 + 0) * DD + d]);
        float w1 = __ldg(&W[(i4 * 4 + 1) * DD + d]);
        float w2 = __ldg(&W[(i4 * 4 + 2) * DD + d]);
        float w3 = __ldg(&W[(i4 * 4 + 3) * DD + d]);
        a0 += f0.x * w0 + f0.y * w1 + f0.z * w2 + f0.w * w3;
        a1 += f1.x * w0 + f1.y * w1 + f1.z * w2 + f1.w * w3;
        a2 += f2.x * w0 + f2.y * w1 + f2.z * w2 + f2.w * w3;
        a3 += f3.x * w0 + f3.y * w1 + f3.z * w2 + f3.w * w3;
    }
    g_P[(row0 + g) * DD + d]      = a0;
    g_P[(row0 + g + 4) * DD + d]  = a1;
    g_P[(row0 + g + 8) * DD + d]  = a2;
    g_P[(row0 + g + 12) * DD + d] = a3;
    int r = threadIdx.x >> 4, t = threadIdx.x & 15;
    float sm = 0.f;
    for (int i = t; i < II; i += 16) sm += shU[r][i];
    sm += __shfl_xor_sync(0xffffffffu, sm, 8);
    sm += __shfl_xor_sync(0xffffffffu, sm, 4);
    sm += __shfl_xor_sync(0xffffffffu, sm, 2);
    sm += __shfl_xor_sync(0xffffffffu, sm, 1);
    if (t == 0) g_Su[row0 + r] = sm;
}

// ---------------------------------------------------------------------------
// Iter-0 shortcut: c0[b,s] = mask/128 is n-independent.
// T0[b,d] = sum_s c0*P[b,s,d] -> g_T[b*DD+d];  q0[b] = sum_s c0*Su -> g_q[b].
// grid = 32 (one per b).
// ---------------------------------------------------------------------------
__global__ void __launch_bounds__(256) k_A0(const float* __restrict__ mask) {
    __shared__ float shT[4][64];
    __shared__ float shQ[4];
    int b = blockIdx.x;
    int d = threadIdx.x & 63, g = threadIdx.x >> 6;
    const float* Pb = &g_P[b * SS * DD];
    float a = 0.f, q = 0.f;
    for (int j = 0; j < 32; j++) {
        int s = g * 32 + j;
        float c = mask[b * SS + s] * (1.0f / 128.0f);
        a += c * Pb[s * DD + d];
        q += c * g_Su[b * SS + s];
    }
    shT[g][d] = a;
    if (d == 0) shQ[g] = q;
    __syncthreads();
    if (threadIdx.x < 64) {
        g_T[b * DD + threadIdx.x] =
            shT[0][threadIdx.x] + shT[1][threadIdx.x] +
            shT[2][threadIdx.x] + shT[3][threadIdx.x];
        if (threadIdx.x == 0) g_q[b] = shQ[0] + shQ[1] + shQ[2] + shQ[3];
    }
}

// ---------------------------------------------------------------------------
// Output terms 1+2, s-split halves (it >= 1 only).
// grid = 32 b * 8 ntile * 2 half = 512.
// ---------------------------------------------------------------------------
__global__ void __launch_bounds__(256) k_outA() {
    __shared__ float  shP[64 * DD];     // 16 KB
    __shared__ float4 shC4[16 * 16];
    __shared__ float4 shSu4[16];
    int blk  = blockIdx.x;
    int half = blk & 1;
    int n0   = ((blk >> 1) & 7) * 16;
    int b    = blk >> 4;
    int sb   = half * 64;
    for (int idx = threadIdx.x; idx < 64 * 16; idx += 256)
        *(float4*)&shP[idx * 4] = *(const float4*)&g_P[(b * SS + sb) * DD + idx * 4];
    for (int idx = threadIdx.x; idx < 16 * 16; idx += 256) {
        int nr = idx >> 4, sc = idx & 15;
        shC4[idx] = *(const float4*)&g_C[(b * NC + n0 + nr) * SS + sb + sc * 4];
    }
    if (threadIdx.x < 16)
        shSu4[threadIdx.x] = *(const float4*)&g_Su[b * SS + sb + threadIdx.x * 4];
    __syncthreads();
    int d = threadIdx.x & 63, g = threadIdx.x >> 6;
    const float4* c0 = &shC4[(g * 4 + 0) * 16];
    const float4* c1 = &shC4[(g * 4 + 1) * 16];
    const float4* c2 = &shC4[(g * 4 + 2) * 16];
    const float4* c3 = &shC4[(g * 4 + 3) * 16];
    float a0 = 0, a1 = 0, a2 = 0, a3 = 0, q0 = 0, q1 = 0, q2 = 0, q3 = 0;
    #pragma unroll
    for (int s4 = 0; s4 < 16; s4++) {
        float4 f0 = c0[s4], f1 = c1[s4], f2 = c2[s4], f3 = c3[s4];
        float4 su = shSu4[s4];
        float p0 = shP[(s4 * 4 + 0) * DD + d];
        float p1 = shP[(s4 * 4 + 1) * DD + d];
        float p2 = shP[(s4 * 4 + 2) * DD + d];
        float p3 = shP[(s4 * 4 + 3) * DD + d];
        a0 += f0.x * p0 + f0.y * p1 + f0.z * p2 + f0.w * p3;
        a1 += f1.x * p0 + f1.y * p1 + f1.z * p2 + f1.w * p3;
        a2 += f2.x * p0 + f2.y * p1 + f2.z * p2 + f2.w * p3;
        a3 += f3.x * p0 + f3.y * p1 + f3.z * p2 + f3.w * p3;
        q0 += f0.x * su.x + f0.y * su.y + f0.z * su.z + f0.w * su.w;
        q1 += f1.x * su.x + f1.y * su.y + f1.z * su.z + f1.w * su.w;
        q2 += f2.x * su.x + f2.y * su.y + f2.z * su.z + f2.w * su.w;
        q3 += f3.x * su.x + f3.y * su.y + f3.z * su.z + f3.w * su.w;
    }
    int nb = n0 + g * 4;
    float* T = g_T + half * TOFF;
    T[(b * NC + nb + 0) * DD + d] = a0 + q0 * g_PE1[(nb + 0) * DD + d];
    T[(b * NC + nb + 1) * DD + d] = a1 + q1 * g_PE1[(nb + 1) * DD + d];
    T[(b * NC + nb + 2) * DD + d] = a2 + q2 * g_PE1[(nb + 2) * DD + d];
    T[(b * NC + nb + 3) * DD + d] = a3 + q3 * g_PE1[(nb + 3) * DD + d];
}

// ---------------------------------------------------------------------------
// Output term 3 + squash + fused logit term 3.
// grid = 128 n * 4 btile = 512; 8 b per block. shPE2 pitched to 68.
// it0: c from mask/128, T from (T0[b,d] + q0[b]*PE1[n,d]).
// ---------------------------------------------------------------------------
__global__ void __launch_bounds__(256) k_outB(float* __restrict__ dst, int final_,
                                              int it0, const float* __restrict__ mask) {
    __shared__ float  shPE2[SS * 68];   // 34.8 KB
    __shared__ float4 shC4[8 * 32];
    __shared__ float  shV[8 * DD];      // 2 KB
    __shared__ float  shRed[4][2][2];
    int n  = blockIdx.x >> 2;
    int b0 = (blockIdx.x & 3) * 8;
    float* Vout = final_ ? dst : g_V;
    for (int idx = threadIdx.x; idx < SS * 16; idx += 256) {
        int s = idx >> 4, c = idx & 15;
        *(float4*)&shPE2[s * 68 + c * 4] = *(const float4*)&g_PE2[s * OD + n * DD + c * 4];
    }
    for (int idx = threadIdx.x; idx < 8 * 32; idx += 256) {
        int bl = idx >> 5, sc = idx & 31;
        if (it0) {
            float4 m = *(const float4*)&mask[(b0 + bl) * SS + sc * 4];
            shC4[idx] = make_float4(m.x * (1.0f / 128.0f), m.y * (1.0f / 128.0f),
                                    m.z * (1.0f / 128.0f), m.w * (1.0f / 128.0f));
        } else {
            shC4[idx] = *(const float4*)&g_C[((b0 + bl) * NC + n) * SS + sc * 4];
        }
    }
    __syncthreads();
    int d = threadIdx.x & 63, g = threadIdx.x >> 6;
    int lane = threadIdx.x & 31, wig = (threadIdx.x >> 5) & 1;
    const float4* c0 = &shC4[(g * 2 + 0) * 32];
    const float4* c1 = &shC4[(g * 2 + 1) * 32];
    float a0 = 0, a1 = 0;
    #pragma unroll
    for (int s4 = 0; s4 < 32; s4++) {
        float4 f0 = c0[s4], f1 = c1[s4];
        float p0 = shPE2[(s4 * 4 + 0) * 68 + d];
        float p1 = shPE2[(s4 * 4 + 1) * 68 + d];
        float p2 = shPE2[(s4 * 4 + 2) * 68 + d];
        float p3 = shPE2[(s4 * 4 + 3) * 68 + d];
        a0 += f0.x * p0 + f0.y * p1 + f0.z * p2 + f0.w * p3;
        a1 += f1.x * p0 + f1.y * p1 + f1.z * p2 + f1.w * p3;
    }
    int bA = b0 + g * 2, bBd = bA + 1;
    float val0, val1;
    if (it0) {
        float pe = g_PE1[n * DD + d];
        val0 = g_T[bA  * DD + d] + g_q[bA]  * pe + a0;
        val1 = g_T[bBd * DD + d] + g_q[bBd] * pe + a1;
    } else {
        val0 = g_T[(bA * NC + n) * DD + d] + g_T[TOFF + (bA * NC + n) * DD + d] + a0;
        val1 = g_T[(bBd * NC + n) * DD + d] + g_T[TOFF + (bBd * NC + n) * DD + d] + a1;
    }
    float ss0 = val0 * val0, ss1 = val1 * val1;
    #pragma unroll
    for (int off = 16; off; off >>= 1) {
        ss0 += __shfl_xor_sync(0xffffffffu, ss0, off);
        ss1 += __shfl_xor_sync(0xffffffffu, ss1, off);
    }
    if (lane == 0) { shRed[g][wig][0] = ss0; shRed[g][wig][1] = ss1; }
    __syncthreads();
    float t0 = shRed[g][0][0] + shRed[g][1][0];
    float t1 = shRed[g][0][1] + shRed[g][1][1];
    float sc0 = t0 / (1.0f + t0) * rsqrtf(t0 + 1e-7f);
    float sc1 = t1 / (1.0f + t1) * rsqrtf(t1 + 1e-7f);
    float v0w = sc0 * val0, v1w = sc1 * val1;
    Vout[(bA  * NC + n) * DD + d] = v0w;
    Vout[(bBd * NC + n) * DD + d] = v1w;
    if (final_) return;
    shV[(g * 2 + 0) * DD + d] = v0w;
    shV[(g * 2 + 1) * DD + d] = v1w;
    __syncthreads();
    // Phase 2: logit term 3 for this (n, b-tile)
    int s = threadIdx.x & 127, h = threadIdx.x >> 7;
    int bl = h * 4;
    const float4* pr = (const float4*)&shPE2[s * 68];
    const float4* w0 = (const float4*)&shV[(bl + 0) * DD];
    const float4* w1 = (const float4*)&shV[(bl + 1) * DD];
    const float4* w2 = (const float4*)&shV[(bl + 2) * DD];
    const float4* w3 = (const float4*)&shV[(bl + 3) * DD];
    float r0 = 0, r1 = 0, r2 = 0, r3 = 0;
    #pragma unroll
    for (int d4 = 0; d4 < 16; d4++) {
        float4 p = pr[d4];
        float4 x0 = w0[d4], x1 = w1[d4], x2 = w2[d4], x3 = w3[d4];
        r0 += p.x * x0.x + p.y * x0.y + p.z * x0.z + p.w * x0.w;
        r1 += p.x * x1.x + p.y * x1.y + p.z * x1.z + p.w * x1.w;
        r2 += p.x * x2.x + p.y * x2.y + p.z * x2.z + p.w * x2.w;
        r3 += p.x * x3.x + p.y * x3.y + p.z * x3.z + p.w * x3.w;
    }
    g_Bl[((b0 + bl + 0) * NC + n) * SS + s] = r0;
    g_Bl[((b0 + bl + 1) * NC + n) * SS + s] = r1;
    g_Bl[((b0 + bl + 2) * NC + n) * SS + s] = r2;
    g_Bl[((b0 + bl + 3) * NC + n) * SS + s] = r3;
}

// ---------------------------------------------------------------------------
// Logit terms 1+2 (accumulate onto term 3). grid = 32 b * 16 ntile = 512.
// ---------------------------------------------------------------------------
__global__ void __launch_bounds__(256) k_bA() {
    __shared__ float shP[SS * 68];   // 34.8 KB
    __shared__ float shV[8 * DD];
    __shared__ float shSu[SS];
    __shared__ float shSc[8];
    int b  = blockIdx.x >> 4;
    int n0 = (blockIdx.x & 15) * 8;
    for (int idx = threadIdx.x; idx < SS * 16; idx += 256) {
        int s = idx >> 4, c = idx & 15;
        *(float4*)&shP[s * 68 + c * 4] = *(const float4*)&g_P[(b * SS + s) * DD + c * 4];
    }
    for (int idx = threadIdx.x; idx < 8 * 16; idx += 256)
        *(float4*)&shV[idx * 4] = *(const float4*)&g_V[(b * NC + n0) * DD + idx * 4];
    if (threadIdx.x < SS) shSu[threadIdx.x] = g_Su[b * SS + threadIdx.x];
    __syncthreads();
    {
        int w = threadIdx.x >> 5, lane = threadIdx.x & 31;
        float t = shV[w * DD + lane]      * g_PE1[(n0 + w) * DD + lane]
                + shV[w * DD + 32 + lane] * g_PE1[(n0 + w) * DD + 32 + lane];
        #pragma unroll
        for (int off = 16; off; off >>= 1)
            t += __shfl_xor_sync(0xffffffffu, t, off);
        if (lane == 0) shSc[w] = t;
    }
    __syncthreads();
    int s = threadIdx.x & 127, h = threadIdx.x >> 7;
    int nl = h * 4;
    const float4* pr = (const float4*)&shP[s * 68];
    const float4* v0 = (const float4*)&shV[(nl + 0) * DD];
    const float4* v1 = (const float4*)&shV[(nl + 1) * DD];
    const float4* v2 = (const float4*)&shV[(nl + 2) * DD];
    const float4* v3 = (const float4*)&shV[(nl + 3) * DD];
    float a0 = 0, a1 = 0, a2 = 0, a3 = 0;
    #pragma unroll
    for (int d4 = 0; d4 < 16; d4++) {
        float4 p = pr[d4];
        float4 w0 = v0[d4], w1 = v1[d4], w2 = v2[d4], w3 = v3[d4];
        a0 += p.x * w0.x + p.y * w0.y + p.z * w0.z + p.w * w0.w;
        a1 += p.x * w1.x + p.y * w1.y + p.z * w1.z + p.w * w1.w;
        a2 += p.x * w2.x + p.y * w2.y + p.z * w2.z + p.w * w2.w;
        a3 += p.x * w3.x + p.y * w3.y + p.z * w3.z + p.w * w3.w;
    }
    float su = shSu[s];
    g_Bl[(b * NC + n0 + nl + 0) * SS + s] += a0 + su * shSc[nl + 0];
    g_Bl[(b * NC + n0 + nl + 1) * SS + s] += a1 + su * shSc[nl + 1];
    g_Bl[(b * NC + n0 + nl + 2) * SS + s] += a2 + su * shSc[nl + 2];
    g_Bl[(b * NC + n0 + nl + 3) * SS + s] += a3 + su * shSc[nl + 3];
}

// ---------------------------------------------------------------------------
// Softmax over n. grid = 128, 256 threads (8 warps x 16 n).
// ---------------------------------------------------------------------------
__global__ void __launch_bounds__(256) k_softmax(const float* __restrict__ mask) {
    __shared__ float red[2][8][32];
    int b = blockIdx.x >> 2, s0 = (blockIdx.x & 3) * 32;
    int lane = threadIdx.x & 31, w = threadIdx.x >> 5;
    int s = s0 + lane;
    float v[16];
    float mx = -1e30f;
    #pragma unroll
    for (int j = 0; j < 16; j++) {
        v[j] = g_Bl[(b * NC + w * 16 + j) * SS + s];
        mx = fmaxf(mx, v[j]);
    }
    red[0][w][lane] = mx;
    __syncthreads();
    mx = red[0][0][lane];
    #pragma unroll
    for (int w2 = 1; w2 < 8; w2++) mx = fmaxf(mx, red[0][w2][lane]);
    float sum = 0.f;
    #pragma unroll
    for (int j = 0; j < 16; j++) { v[j] = __expf(v[j] - mx); sum += v[j]; }
    red[1][w][lane] = sum;
    __syncthreads();
    sum = red[1][0][lane];
    #pragma unroll
    for (int w2 = 1; w2 < 8; w2++) sum += red[1][w2][lane];
    float scale = mask[b * SS + s] / sum;
    #pragma unroll
    for (int j = 0; j < 16; j++)
        g_C[(b * NC + w * 16 + j) * SS + s] = v[j] * scale;
}

// ---------------------------------------------------------------------------
extern "C" void kernel_launch(void* const* d_in, const int* in_sizes, int n_in,
                              void* d_out, int out_size) {
    const float* u    = (const float*)d_in[0];
    const float* mask = (const float*)d_in[1];
    const float* W    = (const float*)d_in[2];
    float* out = (float*)d_out;

    k_init<<<288, 256>>>(u, W);
    k_A0<<<32, 256>>>(mask);

    // iteration 0 (c = mask/128, n-independent outA replaced by A0)
    k_outB<<<512, 256>>>(out, 0, 1, mask);
    k_bA<<<512, 256>>>();
    k_softmax<<<128, 256>>>(mask);
    // iteration 1
    k_outA<<<512, 256>>>();
    k_outB<<<512, 256>>>(out, 0, 0, mask);
    k_bA<<<512, 256>>>();
    k_softmax<<<128, 256>>>(mask);
    // iteration 2
    k_outA<<<512, 256>>>();
    k_outB<<<512, 256>>>(out, 1, 0, mask);
}

// round 13
// speedup vs baseline: 1.2897x; 1.0835x over previous
#include <cuda_runtime.h>
#include <math.h>

#define BB 32
#define SS 128
#define NC 128
#define DD 64
#define II 256
#define OD 8192   // NC*DD
#define TOFF (BB*NC*DD)

__device__ float g_PE1[NC * DD];
__device__ float g_PE2[SS * OD];        // 4 MB
__device__ float g_P  [BB * SS * DD];
__device__ float g_Su [BB * SS];
__device__ float g_q  [BB];
__device__ float g_C  [BB * NC * SS];
__device__ float g_T  [2 * BB * NC * DD];
__device__ float g_V  [BB * NC * DD];
__device__ float g_Bl [BB * NC * SS];

// ---------------------------------------------------------------------------
// Init, 288 blocks:
//   0..15   : PE2 via rotation recurrence along s (4096 threads, 1 sincos each)
//   16..31  : PE1 direct
//   32..287 : gemmP (P = u @ W, Su = rowsum(u))
// ---------------------------------------------------------------------------
__global__ void __launch_bounds__(256) k_init(const float* __restrict__ u,
                                              const float* __restrict__ W) {
    __shared__ float shU[16][II];   // gemm branch only
    const float LN1E4 = 9.210340371976184f;
    if (blockIdx.x < 16) {
        int k = blockIdx.x * 256 + threadIdx.x;      // 0..4095
        float th = expf(-(float)k * (LN1E4 / 4096.0f));
        float sv, cv;
        sincosf(th, &sv, &cv);
        float sc = 0.f, cc = 1.f;                    // s = 0
        float2* dst = (float2*)g_PE2;
        #pragma unroll 4
        for (int s = 0; s < SS; s++) {
            dst[s * (OD / 2) + k] = make_float2(sc, cc);
            float ns = sc * cv + cc * sv;
            float nc = cc * cv - sc * sv;
            sc = ns; cc = nc;
        }
        return;
    }
    if (blockIdx.x < 32) {
        int idx = (blockIdx.x - 16) * 256 + threadIdx.x;  // 0..4095
        int n = idx >> 5, kk = idx & 31;
        float th = expf(-(float)kk * (LN1E4 / 32.0f));
        float sv, cv;
        sincosf((float)n * th, &sv, &cv);
        *(float2*)&g_PE1[n * DD + 2 * kk] = make_float2(sv, cv);
        return;
    }
    int row0 = (blockIdx.x - 32) * 16;
    for (int idx = threadIdx.x; idx < 16 * 64; idx += 256) {
        int r = idx >> 6, i = idx & 63;
        *(float4*)&shU[r][i * 4] = *(const float4*)&u[(row0 + r) * II + i * 4];
    }
    __syncthreads();
    int d = threadIdx.x & 63, g = threadIdx.x >> 6;
    const float4* u0 = (const float4*)&shU[g][0];
    const float4* u1 = (const float4*)&shU[g + 4][0];
    const float4* u2 = (const float4*)&shU[g + 8][0];
    const float4* u3 = (const float4*)&shU[g + 12][0];
    float a0 = 0, a1 = 0, a2 = 0, a3 = 0;
    #pragma unroll 8
    for (int i4 = 0; i4 < II / 4; i4++) {
        float4 f0 = u0[i4], f1 = u1[i4], f2 = u2[i4], f3 = u3[i4];
        float w0 = __ldg(&W[(i4 * 4 + 0) * DD + d]);
        float w1 = __ldg(&W[(i4 * 4 + 1) * DD + d]);
        float w2 = __ldg(&W[(i4 * 4 + 2) * DD + d]);
        float w3 = __ldg(&W[(i4 * 4 + 3) * DD + d]);
        a0 += f0.x * w0 + f0.y * w1 + f0.z * w2 + f0.w * w3;
        a1 += f1.x * w0 + f1.y * w1 + f1.z * w2 + f1.w * w3;
        a2 += f2.x * w0 + f2.y * w1 + f2.z * w2 + f2.w * w3;
        a3 += f3.x * w0 + f3.y * w1 + f3.z * w2 + f3.w * w3;
    }
    g_P[(row0 + g) * DD + d]      = a0;
    g_P[(row0 + g + 4) * DD + d]  = a1;
    g_P[(row0 + g + 8) * DD + d]  = a2;
    g_P[(row0 + g + 12) * DD + d] = a3;
    int r = threadIdx.x >> 4, t = threadIdx.x & 15;
    float sm = 0.f;
    for (int i = t; i < II; i += 16) sm += shU[r][i];
    sm += __shfl_xor_sync(0xffffffffu, sm, 8);
    sm += __shfl_xor_sync(0xffffffffu, sm, 4);
    sm += __shfl_xor_sync(0xffffffffu, sm, 2);
    sm += __shfl_xor_sync(0xffffffffu, sm, 1);
    if (t == 0) g_Su[row0 + r] = sm;
}

// ---------------------------------------------------------------------------
// Iter-0 shortcut (c0 n-independent): T0[b,d], q0[b]. grid = 32.
// ---------------------------------------------------------------------------
__global__ void __launch_bounds__(256) k_A0(const float* __restrict__ mask) {
    __shared__ float shT[4][64];
    __shared__ float shQ[4];
    int b = blockIdx.x;
    int d = threadIdx.x & 63, g = threadIdx.x >> 6;
    const float* Pb = &g_P[b * SS * DD];
    float a = 0.f, q = 0.f;
    for (int j = 0; j < 32; j++) {
        int s = g * 32 + j;
        float c = mask[b * SS + s] * (1.0f / 128.0f);
        a += c * Pb[s * DD + d];
        q += c * g_Su[b * SS + s];
    }
    shT[g][d] = a;
    if (d == 0) shQ[g] = q;
    __syncthreads();
    if (threadIdx.x < 64) {
        g_T[b * DD + threadIdx.x] =
            shT[0][threadIdx.x] + shT[1][threadIdx.x] +
            shT[2][threadIdx.x] + shT[3][threadIdx.x];
        if (threadIdx.x == 0) g_q[b] = shQ[0] + shQ[1] + shQ[2] + shQ[3];
    }
}

// ---------------------------------------------------------------------------
// Output terms 1+2, s-split halves. 512 threads; 32 n per block.
// grid = 32 b * 4 ntile * 2 half = 256.
// ---------------------------------------------------------------------------
__global__ void __launch_bounds__(512) k_outA() {
    __shared__ float  shP[64 * DD];     // 16 KB (half of P_b)
    __shared__ float4 shC4[32 * 16];    // 32 n x 64 s -> 8 KB
    __shared__ float4 shSu4[16];
    int half = blockIdx.x & 1;
    int n0   = ((blockIdx.x >> 1) & 3) * 32;
    int b    = blockIdx.x >> 3;
    int sb   = half * 64;
    for (int idx = threadIdx.x; idx < 64 * 16; idx += 512)
        *(float4*)&shP[idx * 4] = *(const float4*)&g_P[(b * SS + sb) * DD + idx * 4];
    {
        int idx = threadIdx.x;               // 512 = 32*16, one each
        int nr = idx >> 4, sc = idx & 15;
        shC4[idx] = *(const float4*)&g_C[(b * NC + n0 + nr) * SS + sb + sc * 4];
    }
    if (threadIdx.x < 16)
        shSu4[threadIdx.x] = *(const float4*)&g_Su[b * SS + sb + threadIdx.x * 4];
    __syncthreads();
    int d = threadIdx.x & 63, g = threadIdx.x >> 6;   // g in 0..7, 4 n each
    const float4* c0 = &shC4[(g * 4 + 0) * 16];
    const float4* c1 = &shC4[(g * 4 + 1) * 16];
    const float4* c2 = &shC4[(g * 4 + 2) * 16];
    const float4* c3 = &shC4[(g * 4 + 3) * 16];
    float a0 = 0, a1 = 0, a2 = 0, a3 = 0, q0 = 0, q1 = 0, q2 = 0, q3 = 0;
    #pragma unroll
    for (int s4 = 0; s4 < 16; s4++) {
        float4 f0 = c0[s4], f1 = c1[s4], f2 = c2[s4], f3 = c3[s4];
        float4 su = shSu4[s4];
        float p0 = shP[(s4 * 4 + 0) * DD + d];
        float p1 = shP[(s4 * 4 + 1) * DD + d];
        float p2 = shP[(s4 * 4 + 2) * DD + d];
        float p3 = shP[(s4 * 4 + 3) * DD + d];
        a0 += f0.x * p0 + f0.y * p1 + f0.z * p2 + f0.w * p3;
        a1 += f1.x * p0 + f1.y * p1 + f1.z * p2 + f1.w * p3;
        a2 += f2.x * p0 + f2.y * p1 + f2.z * p2 + f2.w * p3;
        a3 += f3.x * p0 + f3.y * p1 + f3.z * p2 + f3.w * p3;
        q0 += f0.x * su.x + f0.y * su.y + f0.z * su.z + f0.w * su.w;
        q1 += f1.x * su.x + f1.y * su.y + f1.z * su.z + f1.w * su.w;
        q2 += f2.x * su.x + f2.y * su.y + f2.z * su.z + f2.w * su.w;
        q3 += f3.x * su.x + f3.y * su.y + f3.z * su.z + f3.w * su.w;
    }
    int nb = n0 + g * 4;
    float* T = g_T + half * TOFF;
    T[(b * NC + nb + 0) * DD + d] = a0 + q0 * g_PE1[(nb + 0) * DD + d];
    T[(b * NC + nb + 1) * DD + d] = a1 + q1 * g_PE1[(nb + 1) * DD + d];
    T[(b * NC + nb + 2) * DD + d] = a2 + q2 * g_PE1[(nb + 2) * DD + d];
    T[(b * NC + nb + 3) * DD + d] = a3 + q3 * g_PE1[(nb + 3) * DD + d];
}

// ---------------------------------------------------------------------------
// Output term 3 + squash + fused logit term 3. 512 threads; 16 b per block.
// grid = 128 n * 2 btile = 256. shPE2 pitched to 68.
// Phase 1: thread = (d, b-pair); Phase 2: thread = (s, b-quad).
// ---------------------------------------------------------------------------
__global__ void __launch_bounds__(512) k_outB(float* __restrict__ dst, int final_,
                                              int it0, const float* __restrict__ mask) {
    __shared__ float  shPE2[SS * 68];   // 34.8 KB
    __shared__ float4 shC4[16 * 32];    // 16 b x 128 s -> 8 KB
    __shared__ float  shV[16 * DD];     // 4 KB
    __shared__ float  shRed[8][2];
    int n  = blockIdx.x >> 1;
    int b0 = (blockIdx.x & 1) * 16;
    float* Vout = final_ ? dst : g_V;
    for (int idx = threadIdx.x; idx < SS * 16; idx += 512) {
        int s = idx >> 4, c = idx & 15;
        *(float4*)&shPE2[s * 68 + c * 4] = *(const float4*)&g_PE2[s * OD + n * DD + c * 4];
    }
    {
        int idx = threadIdx.x;              // 512 = 16*32, one each
        int bl = idx >> 5, sc = idx & 31;
        if (it0) {
            float4 m = *(const float4*)&mask[(b0 + bl) * SS + sc * 4];
            shC4[idx] = make_float4(m.x * (1.0f / 128.0f), m.y * (1.0f / 128.0f),
                                    m.z * (1.0f / 128.0f), m.w * (1.0f / 128.0f));
        } else {
            shC4[idx] = *(const float4*)&g_C[((b0 + bl) * NC + n) * SS + sc * 4];
        }
    }
    __syncthreads();
    int d = threadIdx.x & 63, g = threadIdx.x >> 6;   // g in 0..7, 2 b each
    int lane = threadIdx.x & 31, wig = (threadIdx.x >> 5) & 1;
    const float4* c0 = &shC4[(g * 2 + 0) * 32];
    const float4* c1 = &shC4[(g * 2 + 1) * 32];
    float a0 = 0, a1 = 0;
    #pragma unroll
    for (int s4 = 0; s4 < 32; s4++) {
        float4 f0 = c0[s4], f1 = c1[s4];
        float p0 = shPE2[(s4 * 4 + 0) * 68 + d];
        float p1 = shPE2[(s4 * 4 + 1) * 68 + d];
        float p2 = shPE2[(s4 * 4 + 2) * 68 + d];
        float p3 = shPE2[(s4 * 4 + 3) * 68 + d];
        a0 += f0.x * p0 + f0.y * p1 + f0.z * p2 + f0.w * p3;
        a1 += f1.x * p0 + f1.y * p1 + f1.z * p2 + f1.w * p3;
    }
    int bA = b0 + g * 2, bBd = bA + 1;
    float val0, val1;
    if (it0) {
        float pe = g_PE1[n * DD + d];
        val0 = g_T[bA  * DD + d] + g_q[bA]  * pe + a0;
        val1 = g_T[bBd * DD + d] + g_q[bBd] * pe + a1;
    } else {
        val0 = g_T[(bA * NC + n) * DD + d] + g_T[TOFF + (bA * NC + n) * DD + d] + a0;
        val1 = g_T[(bBd * NC + n) * DD + d] + g_T[TOFF + (bBd * NC + n) * DD + d] + a1;
    }
    float ss0 = val0 * val0, ss1 = val1 * val1;
    #pragma unroll
    for (int off = 16; off; off >>= 1) {
        ss0 += __shfl_xor_sync(0xffffffffu, ss0, off);
        ss1 += __shfl_xor_sync(0xffffffffu, ss1, off);
    }
    if (lane == 0) { shRed[g][wig] = ss0; }
    __shared__ float shRed1[8][2];
    if (lane == 1) { /* placeholder to keep structure simple */ }
    if (lane == 0) { shRed1[g][wig] = ss1; }
    __syncthreads();
    float t0 = shRed[g][0] + shRed[g][1];
    float t1 = shRed1[g][0] + shRed1[g][1];
    float sc0 = t0 / (1.0f + t0) * rsqrtf(t0 + 1e-7f);
    float sc1 = t1 / (1.0f + t1) * rsqrtf(t1 + 1e-7f);
    float v0w = sc0 * val0, v1w = sc1 * val1;
    Vout[(bA  * NC + n) * DD + d] = v0w;
    Vout[(bBd * NC + n) * DD + d] = v1w;
    if (final_) return;
    shV[(g * 2 + 0) * DD + d] = v0w;
    shV[(g * 2 + 1) * DD + d] = v1w;
    __syncthreads();
    // Phase 2: Bl[b,n,s] = sum_d V*PE2 for this (n, 16-b tile)
    int s = threadIdx.x & 127, h = threadIdx.x >> 7;  // h in 0..3, 4 b each
    int bl = h * 4;
    const float4* pr = (const float4*)&shPE2[s * 68];
    const float4* w0 = (const float4*)&shV[(bl + 0) * DD];
    const float4* w1 = (const float4*)&shV[(bl + 1) * DD];
    const float4* w2 = (const float4*)&shV[(bl + 2) * DD];
    const float4* w3 = (const float4*)&shV[(bl + 3) * DD];
    float r0 = 0, r1 = 0, r2 = 0, r3 = 0;
    #pragma unroll
    for (int d4 = 0; d4 < 16; d4++) {
        float4 p = pr[d4];
        float4 x0 = w0[d4], x1 = w1[d4], x2 = w2[d4], x3 = w3[d4];
        r0 += p.x * x0.x + p.y * x0.y + p.z * x0.z + p.w * x0.w;
        r1 += p.x * x1.x + p.y * x1.y + p.z * x1.z + p.w * x1.w;
        r2 += p.x * x2.x + p.y * x2.y + p.z * x2.z + p.w * x2.w;
        r3 += p.x * x3.x + p.y * x3.y + p.z * x3.z + p.w * x3.w;
    }
    g_Bl[((b0 + bl + 0) * NC + n) * SS + s] = r0;
    g_Bl[((b0 + bl + 1) * NC + n) * SS + s] = r1;
    g_Bl[((b0 + bl + 2) * NC + n) * SS + s] = r2;
    g_Bl[((b0 + bl + 3) * NC + n) * SS + s] = r3;
}

// ---------------------------------------------------------------------------
// Logit terms 1+2 (accumulate onto term 3). 512 threads; 16 n per block.
// grid = 32 b * 8 ntile = 256.
// ---------------------------------------------------------------------------
__global__ void __launch_bounds__(512) k_bA() {
    __shared__ float shP[SS * 68];   // 34.8 KB
    __shared__ float shV[16 * DD];   // 4 KB
    __shared__ float shSu[SS];
    __shared__ float shSc[16];
    int b  = blockIdx.x >> 3;
    int n0 = (blockIdx.x & 7) * 16;
    for (int idx = threadIdx.x; idx < SS * 16; idx += 512) {
        int s = idx >> 4, c = idx & 15;
        *(float4*)&shP[s * 68 + c * 4] = *(const float4*)&g_P[(b * SS + s) * DD + c * 4];
    }
    for (int idx = threadIdx.x; idx < 16 * 16; idx += 512)
        *(float4*)&shV[idx * 4] = *(const float4*)&g_V[(b * NC + n0) * DD + idx * 4];
    if (threadIdx.x < SS) shSu[threadIdx.x] = g_Su[b * SS + threadIdx.x];
    __syncthreads();
    {
        // warp w (0..15) computes shSc[w] = dot(V[n0+w], PE1[n0+w])
        int w = threadIdx.x >> 5, lane = threadIdx.x & 31;
        float t = shV[w * DD + lane]      * g_PE1[(n0 + w) * DD + lane]
                + shV[w * DD + 32 + lane] * g_PE1[(n0 + w) * DD + 32 + lane];
        #pragma unroll
        for (int off = 16; off; off >>= 1)
            t += __shfl_xor_sync(0xffffffffu, t, off);
        if (lane == 0) shSc[w] = t;
    }
    __syncthreads();
    int s = threadIdx.x & 127, h = threadIdx.x >> 7;  // h in 0..3, 4 n each
    int nl = h * 4;
    const float4* pr = (const float4*)&shP[s * 68];
    const float4* v0 = (const float4*)&shV[(nl + 0) * DD];
    const float4* v1 = (const float4*)&shV[(nl + 1) * DD];
    const float4* v2 = (const float4*)&shV[(nl + 2) * DD];
    const float4* v3 = (const float4*)&shV[(nl + 3) * DD];
    float a0 = 0, a1 = 0, a2 = 0, a3 = 0;
    #pragma unroll
    for (int d4 = 0; d4 < 16; d4++) {
        float4 p = pr[d4];
        float4 w0 = v0[d4], w1 = v1[d4], w2 = v2[d4], w3 = v3[d4];
        a0 += p.x * w0.x + p.y * w0.y + p.z * w0.z + p.w * w0.w;
        a1 += p.x * w1.x + p.y * w1.y + p.z * w1.z + p.w * w1.w;
        a2 += p.x * w2.x + p.y * w2.y + p.z * w2.z + p.w * w2.w;
        a3 += p.x * w3.x + p.y * w3.y + p.z * w3.z + p.w * w3.w;
    }
    float su = shSu[s];
    g_Bl[(b * NC + n0 + nl + 0) * SS + s] += a0 + su * shSc[nl + 0];
    g_Bl[(b * NC + n0 + nl + 1) * SS + s] += a1 + su * shSc[nl + 1];
    g_Bl[(b * NC + n0 + nl + 2) * SS + s] += a2 + su * shSc[nl + 2];
    g_Bl[(b * NC + n0 + nl + 3) * SS + s] += a3 + su * shSc[nl + 3];
}

// ---------------------------------------------------------------------------
// Softmax over n. grid = 128, 256 threads (8 warps x 16 n).
// ---------------------------------------------------------------------------
__global__ void __launch_bounds__(256) k_softmax(const float* __restrict__ mask) {
    __shared__ float red[2][8][32];
    int b = blockIdx.x >> 2, s0 = (blockIdx.x & 3) * 32;
    int lane = threadIdx.x & 31, w = threadIdx.x >> 5;
    int s = s0 + lane;
    float v[16];
    float mx = -1e30f;
    #pragma unroll
    for (int j = 0; j < 16; j++) {
        v[j] = g_Bl[(b * NC + w * 16 + j) * SS + s];
        mx = fmaxf(mx, v[j]);
    }
    red[0][w][lane] = mx;
    __syncthreads();
    mx = red[0][0][lane];
    #pragma unroll
    for (int w2 = 1; w2 < 8; w2++) mx = fmaxf(mx, red[0][w2][lane]);
    float sum = 0.f;
    #pragma unroll
    for (int j = 0; j < 16; j++) { v[j] = __expf(v[j] - mx); sum += v[j]; }
    red[1][w][lane] = sum;
    __syncthreads();
    sum = red[1][0][lane];
    #pragma unroll
    for (int w2 = 1; w2 < 8; w2++) sum += red[1][w2][lane];
    float scale = mask[b * SS + s] / sum;
    #pragma unroll
    for (int j = 0; j < 16; j++)
        g_C[(b * NC + w * 16 + j) * SS + s] = v[j] * scale;
}

// ---------------------------------------------------------------------------
extern "C" void kernel_launch(void* const* d_in, const int* in_sizes, int n_in,
                              void* d_out, int out_size) {
    const float* u    = (const float*)d_in[0];
    const float* mask = (const float*)d_in[1];
    const float* W    = (const float*)d_in[2];
    float* out = (float*)d_out;

    k_init<<<288, 256>>>(u, W);
    k_A0<<<32, 256>>>(mask);

    // iteration 0 (c = mask/128; outA replaced by A0)
    k_outB<<<256, 512>>>(out, 0, 1, mask);
    k_bA<<<256, 512>>>();
    k_softmax<<<128, 256>>>(mask);
    // iteration 1
    k_outA<<<256, 512>>>();
    k_outB<<<256, 512>>>(out, 0, 0, mask);
    k_bA<<<256, 512>>>();
    k_softmax<<<128, 256>>>(mask);
    // iteration 2
    k_outA<<<256, 512>>>();
    k_outB<<<256, 512>>>(out, 1, 0, mask);
}